// round 10
// baseline (speedup 1.0000x reference)
#include <cuda_runtime.h>
#include <stdint.h>
#include <math.h>

#define NH 8
#define TS 128
#define DH 64
#define DM 512

typedef unsigned long long u64;
typedef unsigned int u32;

// ---------------- scratch (static device memory; no allocations) ----------------
__device__ float g_k1[2*NH*TS*DH];
__device__ float g_k2[2*NH*TS*DH];
__device__ float g_q [2*NH*TS*DH];
__device__ float g_va[2*NH*TS*DH];
__device__ float g_vb[2*NH*TS*DH];
__device__ float g_z [2*NH*TS*DH];

// packed fp32x2 FMA (ptxas never emits FFMA2 from C++; PTX-only path)
__device__ __forceinline__ u64 fma2(u64 a, u64 b, u64 c) {
    u64 d;
    asm("fma.rn.f32x2 %0, %1, %2, %3;" : "=l"(d) : "l"(a), "l"(b), "l"(c));
    return d;
}
__device__ __forceinline__ void lds2(u64& a, u64& b, u32 addr) {
    asm volatile("ld.shared.v2.u64 {%0, %1}, [%2];" : "=l"(a), "=l"(b) : "r"(addr));
}
__device__ __forceinline__ u64 lds1(u32 addr) {
    u64 a;
    asm volatile("ld.shared.b64 %0, [%1];" : "=l"(a) : "r"(addr));
    return a;
}
__device__ __forceinline__ float2 unpack2(u64 v) {
    float2 f;
    asm("mov.b64 {%0, %1}, %2;" : "=f"(f.x), "=f"(f.y) : "l"(v));
    return f;
}

// Fast exp: scores are tiny (|x| << 1); Taylor deg-8 on |x|<=0.9 (rel err ~1e-6),
// exact expf fallback otherwise (never hit on real data; stale rows are zero-filled).
__device__ __forceinline__ float fast_exp(float x) {
    if (fabsf(x) > 0.9f) return expf(x);
    float r = 1.f/40320.f;
    r = r*x + 1.f/5040.f;
    r = r*x + 1.f/720.f;
    r = r*x + 1.f/120.f;
    r = r*x + 1.f/24.f;
    r = r*x + 1.f/6.f;
    r = r*x + 0.5f;
    r = r*x + 1.f;
    r = r*x + 1.f;
    return r;
}

// ---------------- kernel 1: five projections  out[b,n,p,h] = x[b,p,:] @ W[n,:,h] + bias --------
// grid (20, 16, 2): x = proj*4 + ptile(32p), y = n*2 + hhalf(32h). 128 threads.
// k-paired f32x2: xs[p][36] (k contiguous), ws[h][36] (k contiguous, transposed on load).
// Thread tile 2p x 4h, h interleaved: h = h0 + tx + 8c.
__global__ void proj_kernel(const float* __restrict__ x,
                            const float* __restrict__ Wk1, const float* __restrict__ Wk2,
                            const float* __restrict__ Wq,  const float* __restrict__ Wv12,
                            const float* __restrict__ bk1, const float* __restrict__ bk2,
                            const float* __restrict__ bq)
{
    __shared__ __align__(16) float xs[32*36];
    __shared__ __align__(16) float ws[32*36];
    int tid = threadIdx.x;
    int px = blockIdx.x;
    int ny = blockIdx.y;
    int b  = blockIdx.z;
    int proj = px >> 2;
    int p0 = (px & 3) * 32;
    int n  = ny >> 1;
    int h0 = (ny & 1) * 32;

    const float* W; const float* bias; float* dst;
    if (proj == 0)      { W = Wk1 + n*DM*DH;            bias = bk1 + n*DH; dst = g_k1; }
    else if (proj == 1) { W = Wk2 + n*DM*DH;            bias = bk2 + n*DH; dst = g_k2; }
    else if (proj == 2) { W = Wq  + n*DM*DH;            bias = bq  + n*DH; dst = g_q;  }
    else if (proj == 3) { W = Wv12 + n*2*DM*DH;         bias = 0;          dst = g_va; }
    else                { W = Wv12 + n*2*DM*DH + DM*DH; bias = 0;          dst = g_vb; }

    const float* xb = x + b*TS*DM;
    int ty = tid >> 3;                 // 0..15 -> p = p0 + ty*2 + {0,1}
    int tx = tid & 7;                  // 0..7  -> h = h0 + tx + 8c
    u32 xs_b = (u32)__cvta_generic_to_shared(xs);
    u32 ws_b = (u32)__cvta_generic_to_shared(ws);
    u32 aA0 = xs_b + (ty*2    )*36*4;
    u32 aA1 = xs_b + (ty*2 + 1)*36*4;
    u32 aB0 = ws_b + (tx      )*36*4;
    u32 aB1 = ws_b + (tx +  8 )*36*4;
    u32 aB2 = ws_b + (tx + 16 )*36*4;
    u32 aB3 = ws_b + (tx + 24 )*36*4;

    u64 acc[2][4];
    #pragma unroll
    for (int r = 0; r < 2; r++)
        #pragma unroll
        for (int c = 0; c < 4; c++) acc[r][c] = 0ull;

    for (int k0 = 0; k0 < DM; k0 += 32) {
        #pragma unroll
        for (int r = 0; r < 8; r++) {
            int e = tid + r*128;           // 1024: 32p x 32k
            int pp = e >> 5, kk = e & 31;
            xs[pp*36 + kk] = xb[(p0+pp)*DM + k0 + kk];
        }
        #pragma unroll
        for (int r = 0; r < 8; r++) {
            int e = tid + r*128;           // 1024: 32k x 32h, transposed store
            int kk = e >> 5, hh = e & 31;
            ws[hh*36 + kk] = W[(k0+kk)*DH + h0 + hh];
        }
        __syncthreads();
        #pragma unroll
        for (int k = 0; k < 32; k += 2) {
            u64 a0 = lds1(aA0 + k*4);
            u64 a1 = lds1(aA1 + k*4);
            u64 b0 = lds1(aB0 + k*4);
            u64 b1 = lds1(aB1 + k*4);
            u64 b2 = lds1(aB2 + k*4);
            u64 b3 = lds1(aB3 + k*4);
            acc[0][0] = fma2(a0, b0, acc[0][0]);
            acc[0][1] = fma2(a0, b1, acc[0][1]);
            acc[0][2] = fma2(a0, b2, acc[0][2]);
            acc[0][3] = fma2(a0, b3, acc[0][3]);
            acc[1][0] = fma2(a1, b0, acc[1][0]);
            acc[1][1] = fma2(a1, b1, acc[1][1]);
            acc[1][2] = fma2(a1, b2, acc[1][2]);
            acc[1][3] = fma2(a1, b3, acc[1][3]);
        }
        __syncthreads();
    }
    int bn = b*NH + n;
    #pragma unroll
    for (int r = 0; r < 2; r++) {
        int prow = p0 + ty*2 + r;
        float* o = dst + (bn*TS + prow)*DH + h0;
        #pragma unroll
        for (int c = 0; c < 4; c++) {
            int h = tx + 8*c;
            float2 v = unpack2(acc[r][c]);
            float val = v.x + v.y;
            if (bias) val += bias[h0 + h];
            o[h] = val;
        }
    }
}

// ---------------- kernel 2: per (b,n,q): warp-cooperative 8x8 score tiles, fused z ----------------
// grid (128, 8, 2), 256 threads = 8 warps. Tile (i,j): i<=j, ntiles = T8(T8+1)/2.
// Lane (p,r): rows {s0+p, s0+p+4}, col t0+r. f32x2 inner product via ld.shared.v2.u64.
#define MAXT 136
__global__ __launch_bounds__(256, 2) void attn_kernel(const float* __restrict__ bv12)
{
    extern __shared__ __align__(16) float sm[];
    float* su    = sm;                    // 128 x 68 (phase1: k1*q ; phase2: va)
    float* sk2   = su   + 128*68;         // 128 x 68 (phase1: k2   ; phase2: vb)
    float* spart = sk2  + 128*68;         // MAXT x 16 (row[8], col[8] per tile)
    float* srA   = spart + MAXT*16;       // 128 row sums
    float* scB   = srA  + 128;            // 128 col sums
    float* sred  = scB  + 128;            // 256 z partials
    float* sqv   = sred + 256;            // 64 q-vector
    float* sden  = sqv  + 64;             // 1

    int tid = threadIdx.x;
    int wid = tid >> 5, lane = tid & 31;
    int p = lane >> 3, r = lane & 7;
    int Q = blockIdx.x, n = blockIdx.y, b = blockIdx.z;
    int bn = b*NH + n;

    if (Q < 2) {                          // empty softmax -> all mass on sink -> z = 0
        if (tid < DH) g_z[(bn*TS + Q)*DH + tid] = 0.f;
        return;
    }

    int T8 = (Q + 7) >> 3;
    int ntiles = T8*(T8+1)/2;

    const float4* gq4 = (const float4*)(g_q + (bn*TS + Q)*DH);
    if (tid < 16) ((float4*)sqv)[tid] = gq4[tid];
    __syncthreads();

    const float4* gk14 = (const float4*)(g_k1 + bn*TS*DH);
    const float4* gk24 = (const float4*)(g_k2 + bn*TS*DH);
    float4* su4  = (float4*)su;
    float4* sk24 = (float4*)sk2;
    u32 su_b = (u32)__cvta_generic_to_shared(su);
    u32 sk_b = (u32)__cvta_generic_to_shared(sk2);

    int nload = Q * 16;
    for (int e = tid; e < nload; e += 256) {
        int s = e >> 4, h4 = e & 15;
        float4 qv = ((float4*)sqv)[h4];
        float4 a = gk14[s*16 + h4];
        a.x *= qv.x; a.y *= qv.y; a.z *= qv.z; a.w *= qv.w;
        su4 [s*17 + h4] = a;
        sk24[s*17 + h4] = gk24[s*16 + h4];
    }
    // zero-fill stale rows [Q, 8*T8) so tile math stays on the fast exp path
    int rmax = 8*T8;
    float4 zz = make_float4(0.f,0.f,0.f,0.f);
    for (int e = tid; e < (rmax - Q)*16; e += 256) {
        int s = Q + (e >> 4), h4 = e & 15;
        su4 [s*17 + h4] = zz;
        sk24[s*17 + h4] = zz;
    }
    __syncthreads();

    const float inv = 1.f/64.f;

    for (int tile = wid; tile < ntiles; tile += 8) {
        // decode tile -> (i, j), i <= j, offset j(j+1)/2 (warp-uniform)
        int j = (int)((sqrtf(8.f*(float)tile + 1.f) - 1.f) * 0.5f);
        while ((j+1)*(j+2)/2 <= tile) j++;
        while (j*(j+1)/2 > tile) j--;
        int i = tile - j*(j+1)/2;
        int s0 = i*8, t0 = j*8;

        u32 aA = su_b + (s0 + p)*272;             // 17 float4 * 16B
        u32 aB = aA + 4*272;
        u32 aK = sk_b + (t0 + r)*272;
        u64 c0a = 0ull, c0b = 0ull, c1a = 0ull, c1b = 0ull;
        #pragma unroll
        for (int h4 = 0; h4 < 16; h4++) {
            u64 b0, b1, x0, x1, y0, y1;
            lds2(b0, b1, aK + h4*16);
            lds2(x0, x1, aA + h4*16);
            lds2(y0, y1, aB + h4*16);
            c0a = fma2(x0, b0, c0a); c0b = fma2(x1, b1, c0b);
            c1a = fma2(y0, b0, c1a); c1b = fma2(y1, b1, c1b);
        }
        float2 f0 = unpack2(c0a), f1 = unpack2(c0b);
        float acc0 = (f0.x + f1.x) + (f0.y + f1.y);
        float2 g0 = unpack2(c1a), g1 = unpack2(c1b);
        float acc1 = (g0.x + g1.x) + (g0.y + g1.y);

        int sa = s0 + p, sb = s0 + p + 4, t = t0 + r;
        float e0 = (sa < t && t < Q) ? fast_exp(acc0 * inv) : 0.f;
        float e1 = (sb < t && t < Q) ? fast_exp(acc1 * inv) : 0.f;

        // row sums: reduce over r (8 lanes, same p)
        float r0 = e0, r1 = e1;
        r0 += __shfl_down_sync(0xffffffffu, r0, 4);
        r0 += __shfl_down_sync(0xffffffffu, r0, 2);
        r0 += __shfl_down_sync(0xffffffffu, r0, 1);
        r1 += __shfl_down_sync(0xffffffffu, r1, 4);
        r1 += __shfl_down_sync(0xffffffffu, r1, 2);
        r1 += __shfl_down_sync(0xffffffffu, r1, 1);
        // col sums: reduce over p (4 lanes, stride 8); both sub-rows contribute
        float c = e0 + e1;
        c += __shfl_down_sync(0xffffffffu, c, 16);
        c += __shfl_down_sync(0xffffffffu, c, 8);

        float* pp = spart + tile*16;
        if (r == 0) { pp[p] = r0; pp[p+4] = r1; }
        if (lane < 8) pp[8 + lane] = c;
    }
    __syncthreads();

    // reload su/sk2 with va/vb (tile phase done)
    {
        const float4* gva4 = (const float4*)(g_va + bn*TS*DH);
        const float4* gvb4 = (const float4*)(g_vb + bn*TS*DH);
        for (int e = tid; e < nload; e += 256) {
            int s = e >> 4, h4 = e & 15;
            su4 [s*17 + h4] = gva4[s*16 + h4];
            sk24[s*17 + h4] = gvb4[s*16 + h4];
        }
    }
    // deterministic row/col reduction over compact tile partials
    if (tid < 128) {
        int s = tid, i = s >> 3, pr = s & 7;
        float sum = 0.f;
        if (i < T8) {
            for (int j = i; j < T8; j++)
                sum += spart[(j*(j+1)/2 + i)*16 + pr];
        }
        srA[s] = sum;
    } else {
        int t = tid - 128, j = t >> 3, rr = t & 7;
        float sum = 0.f;
        if (j < T8) {
            int base = (j*(j+1)/2)*16 + 8 + rr;
            for (int i = 0; i <= j; i++) sum += spart[base + i*16];
        }
        scB[t] = sum;
    }
    __syncthreads();

    // z partials: z[h] = sum_s srA[s]*va[s,h] + sum_t scB[t]*vb[t,h]
    {
        int part = tid >> 6;              // 0..3, s-chunk of 32
        int h = tid & 63;
        int s0 = part*32;
        int s1 = s0 + 32; if (s1 > Q) s1 = Q;
        float acc = 0.f;
        for (int s = s0; s < s1; s++)
            acc += srA[s]*su[s*68 + h] + scB[s]*sk2[s*68 + h];
        sred[tid] = acc;
    }
    __syncthreads();
    if (tid < 32) {
        float v = srA[tid] + srA[tid+32] + srA[tid+64] + srA[tid+96];
        #pragma unroll
        for (int o = 16; o > 0; o >>= 1) v += __shfl_down_sync(0xffffffffu, v, o);
        if (tid == 0) sden[0] = v;        // den (sink exp underflows to 0)
    }
    __syncthreads();
    if (tid < DH) {
        float tot = sred[tid] + sred[64+tid] + sred[128+tid] + sred[192+tid];
        g_z[(bn*TS + Q)*DH + tid] = tot/sden[0] + bv12[n*DH + tid];
    }
}

// ---------------- kernel 3: out[b,p,d] = sum_{n,h} z[b,n,p,h] * W_O[n,h,d] + b_O ----------------
// grid (4, 16, 2): [32p x 32d] tile per block, 128 threads, thread = 2p x 4d.
__global__ void out_kernel(const float* __restrict__ Wo, const float* __restrict__ bo,
                           float* __restrict__ out)
{
    __shared__ __align__(16) float zs[32*68];
    __shared__ __align__(16) float ws[64*36];
    int tid = threadIdx.x;
    int p0 = blockIdx.x * 32, d0 = blockIdx.y * 32, b = blockIdx.z;
    int ty = tid >> 3;              // 0..15 -> rows 2ty, 2ty+1
    int tx = tid & 7;               // 0..7  -> d = d0 + tx*4
    float4* zs4 = (float4*)zs;
    float4* ws4 = (float4*)ws;

    float acc[2][4];
    #pragma unroll
    for (int r = 0; r < 2; r++)
        #pragma unroll
        for (int c = 0; c < 4; c++) acc[r][c] = 0.f;

    for (int n = 0; n < NH; n++) {
        const float4* gz4 = (const float4*)(g_z + ((b*NH + n)*TS + p0)*DH);
        #pragma unroll
        for (int r = 0; r < 4; r++) {
            int e = tid + r*128;            // 512 float4: 32p x 16h4
            int p = e >> 4, h4 = e & 15;
            zs4[p*17 + h4] = gz4[p*16 + h4];
        }
        const float* Wn = Wo + n*DH*DM;
        #pragma unroll
        for (int r = 0; r < 4; r++) {
            int e = tid + r*128;            // 512 float4: 64h x 8d4
            int h = e >> 3, d4 = e & 7;
            ws4[h*9 + d4] = *(const float4*)&Wn[h*DM + d0 + d4*4];
        }
        __syncthreads();
        #pragma unroll
        for (int h = 0; h < 64; h++) {
            float4 w = ws4[h*9 + tx];
            float a0 = zs[(ty*2)*68 + h];
            float a1 = zs[(ty*2+1)*68 + h];
            acc[0][0] += a0*w.x; acc[0][1] += a0*w.y; acc[0][2] += a0*w.z; acc[0][3] += a0*w.w;
            acc[1][0] += a1*w.x; acc[1][1] += a1*w.y; acc[1][2] += a1*w.z; acc[1][3] += a1*w.w;
        }
        __syncthreads();
    }
    #pragma unroll
    for (int r = 0; r < 2; r++) {
        int p = p0 + ty*2 + r;
        float* o = out + b*TS*DM + p*DM + d0 + tx*4;
        #pragma unroll
        for (int c = 0; c < 4; c++) o[c] = acc[r][c] + bo[d0 + tx*4 + c];
    }
}

// ---------------- launch ----------------
extern "C" void kernel_launch(void* const* d_in, const int* in_sizes, int n_in,
                              void* d_out, int out_size)
{
    const float* x    = (const float*)d_in[0];
    const float* Wk1  = (const float*)d_in[1];
    const float* Wk2  = (const float*)d_in[2];
    const float* Wq   = (const float*)d_in[3];
    const float* Wv12 = (const float*)d_in[4];
    const float* Wo   = (const float*)d_in[5];
    const float* bk1  = (const float*)d_in[6];
    const float* bk2  = (const float*)d_in[7];
    const float* bq   = (const float*)d_in[8];
    const float* bv12 = (const float*)d_in[9];
    const float* bo   = (const float*)d_in[10];
    float* out = (float*)d_out;

    proj_kernel<<<dim3(20, 16, 2), 128>>>(x, Wk1, Wk2, Wq, Wv12, bk1, bk2, bq);

    int smem2 = (128*68*2 + MAXT*16 + 128 + 128 + 256 + 64 + 4)*(int)sizeof(float);  // ~80.9 KB
    cudaFuncSetAttribute(attn_kernel, cudaFuncAttributeMaxDynamicSharedMemorySize, smem2);
    attn_kernel<<<dim3(128, 8, 2), 256, smem2>>>(bv12);

    out_kernel<<<dim3(4, 16, 2), 128>>>(Wo, bo, out);
}

// round 11
// speedup vs baseline: 1.1582x; 1.1582x over previous
#include <cuda_runtime.h>
#include <stdint.h>
#include <math.h>

#define NH 8
#define TS 128
#define DH 64
#define DM 512

typedef unsigned long long u64;
typedef unsigned int u32;

// ---------------- scratch (static device memory; no allocations) ----------------
__device__ float g_k1[2*NH*TS*DH];
__device__ float g_k2[2*NH*TS*DH];
__device__ float g_q [2*NH*TS*DH];
__device__ float g_va[2*NH*TS*DH];
__device__ float g_vb[2*NH*TS*DH];
__device__ float g_z [2*NH*TS*DH];

// packed fp32x2 ops (PTX-only; ptxas never auto-fuses)
__device__ __forceinline__ u64 fma2(u64 a, u64 b, u64 c) {
    u64 d;
    asm("fma.rn.f32x2 %0, %1, %2, %3;" : "=l"(d) : "l"(a), "l"(b), "l"(c));
    return d;
}
__device__ __forceinline__ u64 mul2(u64 a, u64 b) {
    u64 d;
    asm("mul.rn.f32x2 %0, %1, %2;" : "=l"(d) : "l"(a), "l"(b));
    return d;
}
__device__ __forceinline__ void lds2(u64& a, u64& b, u32 addr) {
    asm volatile("ld.shared.v2.u64 {%0, %1}, [%2];" : "=l"(a), "=l"(b) : "r"(addr));
}
__device__ __forceinline__ float2 unpack2(u64 v) {
    float2 f;
    asm("mov.b64 {%0, %1}, %2;" : "=f"(f.x), "=f"(f.y) : "l"(v));
    return f;
}

// Fast exp: scores are tiny (|x| << 1); Taylor deg-8 on |x|<=0.9 (rel err ~1e-6),
// exact expf fallback otherwise (never hit on real data; stale rows are zero-filled).
__device__ __forceinline__ float fast_exp(float x) {
    if (fabsf(x) > 0.9f) return expf(x);
    float r = 1.f/40320.f;
    r = r*x + 1.f/5040.f;
    r = r*x + 1.f/720.f;
    r = r*x + 1.f/120.f;
    r = r*x + 1.f/24.f;
    r = r*x + 1.f/6.f;
    r = r*x + 0.5f;
    r = r*x + 1.f;
    r = r*x + 1.f;
    return r;
}

// ---------------- kernel 1: five projections (measured-best R7 variant, 35.4us) ----------------
// grid (20, 8, 2): blockIdx.x = proj*4 + ptile ; block computes [32p x 64h], K=512, 128 threads.
__global__ void proj_kernel(const float* __restrict__ x,
                            const float* __restrict__ Wk1, const float* __restrict__ Wk2,
                            const float* __restrict__ Wq,  const float* __restrict__ Wv12,
                            const float* __restrict__ bk1, const float* __restrict__ bk2,
                            const float* __restrict__ bq)
{
    __shared__ __align__(16) float xs[32*33];
    __shared__ __align__(16) float ws[32*68];
    int tid = threadIdx.x;
    int px = blockIdx.x;
    int n  = blockIdx.y;
    int b  = blockIdx.z;
    int proj = px >> 2;
    int p0 = (px & 3) * 32;

    const float* W; const float* bias; float* dst;
    if (proj == 0)      { W = Wk1 + n*DM*DH;            bias = bk1 + n*DH; dst = g_k1; }
    else if (proj == 1) { W = Wk2 + n*DM*DH;            bias = bk2 + n*DH; dst = g_k2; }
    else if (proj == 2) { W = Wq  + n*DM*DH;            bias = bq  + n*DH; dst = g_q;  }
    else if (proj == 3) { W = Wv12 + n*2*DM*DH;         bias = 0;          dst = g_va; }
    else                { W = Wv12 + n*2*DM*DH + DM*DH; bias = 0;          dst = g_vb; }

    const float* xb = x + b*TS*DM;
    int ty = tid >> 4, tx = tid & 15;      // 8 x 16 threads -> 4p x 4h each
    float acc[4][4];
    #pragma unroll
    for (int p = 0; p < 4; p++)
        #pragma unroll
        for (int c = 0; c < 4; c++) acc[p][c] = 0.f;

    for (int k0 = 0; k0 < DM; k0 += 32) {
        #pragma unroll
        for (int r = 0; r < 8; r++) {
            int e = tid + r*128;           // 1024: 32p x 32k
            int pp = e >> 5, kk = e & 31;
            xs[pp*33 + kk] = xb[(p0+pp)*DM + k0 + kk];
        }
        #pragma unroll
        for (int r = 0; r < 16; r++) {
            int e = tid + r*128;           // 2048: 32k x 64h
            int kk = e >> 6, hh = e & 63;
            ws[kk*68 + hh] = W[(k0+kk)*DH + hh];
        }
        __syncthreads();
        #pragma unroll
        for (int k = 0; k < 32; k++) {
            float4 bv = *(const float4*)&ws[k*68 + tx*4];
            #pragma unroll
            for (int p = 0; p < 4; p++) {
                float a = xs[(ty*4+p)*33 + k];
                acc[p][0] += a*bv.x; acc[p][1] += a*bv.y;
                acc[p][2] += a*bv.z; acc[p][3] += a*bv.w;
            }
        }
        __syncthreads();
    }
    int bn = b*NH + n;
    #pragma unroll
    for (int p = 0; p < 4; p++) {
        int prow = p0 + ty*4 + p;
        float* o = dst + (bn*TS + prow)*DH + tx*4;
        #pragma unroll
        for (int c = 0; c < 4; c++) {
            float v = acc[p][c];
            if (bias) v += bias[tx*4 + c];
            o[c] = v;
        }
    }
}

// ---------------- kernel 2: TWO queries per block: raw k1/k2, q folded at tile level ------------
// grid (64, 8, 2), 256 threads = 8 warps. QA=2x, QB=2x+1. Tiles 8x8 over (s,t), i<=j.
// Per tile lane (p,r): prod = k1[s]*k2[t] (f32x2), accA += prod*qA, accB += prod*qB (broadcast q).
#define MAXT 136
__global__ __launch_bounds__(256, 2) void attn_kernel(const float* __restrict__ bv12)
{
    extern __shared__ __align__(16) float sm[];
    float* sk1   = sm;                    // 128 x 68 (phase2: va)
    float* sk2   = sk1  + 128*68;         // 128 x 68 (phase2: vb)
    float* spA   = sk2  + 128*68;         // MAXT x 16 (qA: row[8], col[8])
    float* spB   = spA  + MAXT*16;        // MAXT x 16 (qB)
    float* srA_A = spB  + MAXT*16;        // 128
    float* scB_A = srA_A + 128;           // 128
    float* srA_B = scB_A + 128;           // 128
    float* scB_B = srA_B + 128;           // 128
    float* sred  = scB_B + 128;           // 256
    float* sqA   = sred + 256;            // 64
    float* sqB   = sqA  + 64;             // 64
    float* sden  = sqB  + 64;             // 2

    int tid = threadIdx.x;
    int wid = tid >> 5, lane = tid & 31;
    int p = lane >> 3, r = lane & 7;
    int n = blockIdx.y, b = blockIdx.z;
    int bn = b*NH + n;
    int QA = blockIdx.x*2, QB = QA + 1;

    if (QA == 0) {                        // Q=0,1: empty softmax -> z = 0
        if (tid < 2*DH) g_z[(bn*TS + (tid>>6))*DH + (tid&63)] = 0.f;
        return;
    }

    int T8 = (QB + 7) >> 3;
    int ntiles = T8*(T8+1)/2;

    const float4* gqA = (const float4*)(g_q + (bn*TS + QA)*DH);
    const float4* gqB = (const float4*)(g_q + (bn*TS + QB)*DH);
    if (tid < 16)       ((float4*)sqA)[tid]    = gqA[tid];
    else if (tid < 32)  ((float4*)sqB)[tid-16] = gqB[tid-16];

    const float4* gk14 = (const float4*)(g_k1 + bn*TS*DH);
    const float4* gk24 = (const float4*)(g_k2 + bn*TS*DH);
    float4* sk14 = (float4*)sk1;
    float4* sk24 = (float4*)sk2;
    u32 k1_b = (u32)__cvta_generic_to_shared(sk1);
    u32 k2_b = (u32)__cvta_generic_to_shared(sk2);
    u32 qa_b = (u32)__cvta_generic_to_shared(sqA);
    u32 qb_b = (u32)__cvta_generic_to_shared(sqB);

    int nload = QB * 16;
    for (int e = tid; e < nload; e += 256) {
        int s = e >> 4, h4 = e & 15;
        sk14[s*17 + h4] = gk14[e];
        sk24[s*17 + h4] = gk24[e];
    }
    // zero-fill stale rows [QB, 8*T8) so tile math stays on the fast exp path
    float4 zz = make_float4(0.f,0.f,0.f,0.f);
    for (int e = tid; e < (8*T8 - QB)*16; e += 256) {
        int s = QB + (e >> 4), h4 = e & 15;
        sk14[s*17 + h4] = zz;
        sk24[s*17 + h4] = zz;
    }
    __syncthreads();

    const float inv = 1.f/64.f;

    for (int tile = wid; tile < ntiles; tile += 8) {
        // decode tile -> (i, j), i <= j (warp-uniform)
        int j = (int)((sqrtf(8.f*(float)tile + 1.f) - 1.f) * 0.5f);
        while ((j+1)*(j+2)/2 <= tile) j++;
        while (j*(j+1)/2 > tile) j--;
        int i = tile - j*(j+1)/2;
        int s0 = i*8, t0 = j*8;

        u32 aA = k1_b + (s0 + p)*272;             // 17 float4 * 16B row stride
        u32 aB = aA + 4*272;
        u32 aK = k2_b + (t0 + r)*272;
        u64 A0a=0ull, A0b=0ull, A1a=0ull, A1b=0ull;
        u64 B0a=0ull, B0b=0ull, B1a=0ull, B1b=0ull;
        #pragma unroll
        for (int h4 = 0; h4 < 16; h4++) {
            u64 b0, b1, x0, x1, y0, y1, qa0, qa1, qb0, qb1;
            lds2(b0, b1, aK + h4*16);
            lds2(x0, x1, aA + h4*16);
            lds2(y0, y1, aB + h4*16);
            lds2(qa0, qa1, qa_b + h4*16);          // broadcast
            lds2(qb0, qb1, qb_b + h4*16);          // broadcast
            u64 p0a = mul2(x0, b0), p0b = mul2(x1, b1);
            u64 p1a = mul2(y0, b0), p1b = mul2(y1, b1);
            A0a = fma2(p0a, qa0, A0a); A0b = fma2(p0b, qa1, A0b);
            A1a = fma2(p1a, qa0, A1a); A1b = fma2(p1b, qa1, A1b);
            B0a = fma2(p0a, qb0, B0a); B0b = fma2(p0b, qb1, B0b);
            B1a = fma2(p1a, qb0, B1a); B1b = fma2(p1b, qb1, B1b);
        }
        float2 u0, u1;
        u0 = unpack2(A0a); u1 = unpack2(A0b); float a0A = (u0.x+u1.x)+(u0.y+u1.y);
        u0 = unpack2(A1a); u1 = unpack2(A1b); float a1A = (u0.x+u1.x)+(u0.y+u1.y);
        u0 = unpack2(B0a); u1 = unpack2(B0b); float a0B = (u0.x+u1.x)+(u0.y+u1.y);
        u0 = unpack2(B1a); u1 = unpack2(B1b); float a1B = (u0.x+u1.x)+(u0.y+u1.y);

        int sa = s0 + p, sb = sa + 4, t = t0 + r;
        float e0A = (sa < t && t < QA) ? fast_exp(a0A * inv) : 0.f;
        float e1A = (sb < t && t < QA) ? fast_exp(a1A * inv) : 0.f;
        float e0B = (sa < t && t < QB) ? fast_exp(a0B * inv) : 0.f;
        float e1B = (sb < t && t < QB) ? fast_exp(a1B * inv) : 0.f;

        // row sums: reduce over r (8 lanes, same p)
        float r0A = e0A, r1A = e1A, r0B = e0B, r1B = e1B;
        #pragma unroll
        for (int o = 4; o > 0; o >>= 1) {
            r0A += __shfl_down_sync(0xffffffffu, r0A, o);
            r1A += __shfl_down_sync(0xffffffffu, r1A, o);
            r0B += __shfl_down_sync(0xffffffffu, r0B, o);
            r1B += __shfl_down_sync(0xffffffffu, r1B, o);
        }
        // col sums: reduce over p (4 lanes, stride 8)
        float cA = e0A + e1A, cB = e0B + e1B;
        cA += __shfl_down_sync(0xffffffffu, cA, 16);
        cA += __shfl_down_sync(0xffffffffu, cA, 8);
        cB += __shfl_down_sync(0xffffffffu, cB, 16);
        cB += __shfl_down_sync(0xffffffffu, cB, 8);

        float* ppA = spA + tile*16;
        float* ppB = spB + tile*16;
        if (r == 0) { ppA[p] = r0A; ppA[p+4] = r1A; ppB[p] = r0B; ppB[p+4] = r1B; }
        if (lane < 8) { ppA[8 + lane] = cA; ppB[8 + lane] = cB; }
    }
    __syncthreads();

    // reload sk1/sk2 with va/vb (serves both queries)
    {
        const float4* gva4 = (const float4*)(g_va + bn*TS*DH);
        const float4* gvb4 = (const float4*)(g_vb + bn*TS*DH);
        for (int e = tid; e < nload; e += 256) {
            int s = e >> 4, h4 = e & 15;
            sk14[s*17 + h4] = gva4[e];
            sk24[s*17 + h4] = gvb4[e];
        }
    }
    // deterministic row/col reductions for both queries
    #pragma unroll
    for (int qq = 0; qq < 2; qq++) {
        float* sp  = qq ? spB   : spA;
        float* srA = qq ? srA_B : srA_A;
        float* scB = qq ? scB_B : scB_A;
        if (tid < 128) {
            int s = tid, i = s >> 3, pr = s & 7;
            float sum = 0.f;
            if (i < T8) {
                for (int j = i; j < T8; j++)
                    sum += sp[(j*(j+1)/2 + i)*16 + pr];
            }
            srA[s] = sum;
        } else {
            int t = tid - 128, j = t >> 3, rr = t & 7;
            float sum = 0.f;
            if (j < T8) {
                int base = (j*(j+1)/2)*16 + 8 + rr;
                for (int i2 = 0; i2 <= j; i2++) sum += sp[base + i2*16];
            }
            scB[t] = sum;
        }
    }
    __syncthreads();

    // denominators (warp 0 -> qA, warp 1 -> qB)
    if (tid < 64) {
        int qq = tid >> 5, l = tid & 31;
        const float* srA = qq ? srA_B : srA_A;
        float v = srA[l] + srA[l+32] + srA[l+64] + srA[l+96];
        #pragma unroll
        for (int o = 16; o > 0; o >>= 1) v += __shfl_down_sync(0xffffffffu, v, o);
        if (l == 0) sden[qq] = v;
    }
    __syncthreads();

    // z partials: threads [0,128) -> qA, [128,256) -> qB; 2 s-chunks of 64 each
    {
        int qq = tid >> 7;
        int part = (tid >> 6) & 1;
        int h = tid & 63;
        const float* srA = qq ? srA_B : srA_A;
        const float* scB = qq ? scB_B : scB_A;
        int Qc = qq ? QB : QA;
        int s0c = part*64, s1c = s0c + 64; if (s1c > Qc) s1c = Qc;
        float acc = 0.f;
        for (int s = s0c; s < s1c; s++)
            acc += srA[s]*sk1[s*68 + h] + scB[s]*sk2[s*68 + h];
        sred[tid] = acc;
    }
    __syncthreads();
    if (tid < 128) {
        int qq = tid >> 6, h = tid & 63;
        float tot = sred[qq*128 + h] + sred[qq*128 + 64 + h];
        int Qc = qq ? QB : QA;
        g_z[(bn*TS + Qc)*DH + h] = tot/sden[qq] + bv12[n*DH + h];
    }
}

// ---------------- kernel 3: out[b,p,d] = sum_{n,h} z[b,n,p,h] * W_O[n,h,d] + b_O ----------------
// grid (4, 16, 2): [32p x 32d] tile per block, 128 threads, thread = 2p x 4d.
__global__ void out_kernel(const float* __restrict__ Wo, const float* __restrict__ bo,
                           float* __restrict__ out)
{
    __shared__ __align__(16) float zs[32*68];
    __shared__ __align__(16) float ws[64*36];
    int tid = threadIdx.x;
    int p0 = blockIdx.x * 32, d0 = blockIdx.y * 32, b = blockIdx.z;
    int ty = tid >> 3;              // 0..15 -> rows 2ty, 2ty+1
    int tx = tid & 7;               // 0..7  -> d = d0 + tx*4
    float4* zs4 = (float4*)zs;
    float4* ws4 = (float4*)ws;

    float acc[2][4];
    #pragma unroll
    for (int r = 0; r < 2; r++)
        #pragma unroll
        for (int c = 0; c < 4; c++) acc[r][c] = 0.f;

    for (int n = 0; n < NH; n++) {
        const float4* gz4 = (const float4*)(g_z + ((b*NH + n)*TS + p0)*DH);
        #pragma unroll
        for (int r = 0; r < 4; r++) {
            int e = tid + r*128;            // 512 float4: 32p x 16h4
            int p = e >> 4, h4 = e & 15;
            zs4[p*17 + h4] = gz4[p*16 + h4];
        }
        const float* Wn = Wo + n*DH*DM;
        #pragma unroll
        for (int r = 0; r < 4; r++) {
            int e = tid + r*128;            // 512 float4: 64h x 8d4
            int h = e >> 3, d4 = e & 7;
            ws4[h*9 + d4] = *(const float4*)&Wn[h*DM + d0 + d4*4];
        }
        __syncthreads();
        #pragma unroll
        for (int h = 0; h < 64; h++) {
            float4 w = ws4[h*9 + tx];
            float a0 = zs[(ty*2)*68 + h];
            float a1 = zs[(ty*2+1)*68 + h];
            acc[0][0] += a0*w.x; acc[0][1] += a0*w.y; acc[0][2] += a0*w.z; acc[0][3] += a0*w.w;
            acc[1][0] += a1*w.x; acc[1][1] += a1*w.y; acc[1][2] += a1*w.z; acc[1][3] += a1*w.w;
        }
        __syncthreads();
    }
    #pragma unroll
    for (int r = 0; r < 2; r++) {
        int p = p0 + ty*2 + r;
        float* o = out + b*TS*DM + p*DM + d0 + tx*4;
        #pragma unroll
        for (int c = 0; c < 4; c++) o[c] = acc[r][c] + bo[d0 + tx*4 + c];
    }
}

// ---------------- launch ----------------
extern "C" void kernel_launch(void* const* d_in, const int* in_sizes, int n_in,
                              void* d_out, int out_size)
{
    const float* x    = (const float*)d_in[0];
    const float* Wk1  = (const float*)d_in[1];
    const float* Wk2  = (const float*)d_in[2];
    const float* Wq   = (const float*)d_in[3];
    const float* Wv12 = (const float*)d_in[4];
    const float* Wo   = (const float*)d_in[5];
    const float* bk1  = (const float*)d_in[6];
    const float* bk2  = (const float*)d_in[7];
    const float* bq   = (const float*)d_in[8];
    const float* bv12 = (const float*)d_in[9];
    const float* bo   = (const float*)d_in[10];
    float* out = (float*)d_out;

    proj_kernel<<<dim3(20, 8, 2), 128>>>(x, Wk1, Wk2, Wq, Wv12, bk1, bk2, bq);

    int smem2 = (2*128*68 + 2*MAXT*16 + 4*128 + 256 + 64 + 64 + 2)*(int)sizeof(float); // 90632 B
    cudaFuncSetAttribute(attn_kernel, cudaFuncAttributeMaxDynamicSharedMemorySize, smem2);
    attn_kernel<<<dim3(64, 8, 2), 256, smem2>>>(bv12);

    out_kernel<<<dim3(4, 16, 2), 128>>>(Wo, bo, out);
}

// round 12
// speedup vs baseline: 1.2231x; 1.0560x over previous
#include <cuda_runtime.h>
#include <stdint.h>
#include <math.h>

#define NH 8
#define TS 128
#define DH 64
#define DM 512

typedef unsigned long long u64;
typedef unsigned int u32;

// ---------------- scratch (static device memory; no allocations) ----------------
__device__ float g_part[10*131072];   // [ksplit(2)][proj(5)][bn(16)][p(128)][h(64)]
__device__ float g_k1[2*NH*TS*DH];
__device__ float g_k2[2*NH*TS*DH];
__device__ float g_q [2*NH*TS*DH];
__device__ float g_va[2*NH*TS*DH];
__device__ float g_vb[2*NH*TS*DH];
__device__ float g_z [2*NH*TS*DH];

// packed fp32x2 ops (PTX-only; ptxas never auto-fuses)
__device__ __forceinline__ u64 fma2(u64 a, u64 b, u64 c) {
    u64 d;
    asm("fma.rn.f32x2 %0, %1, %2, %3;" : "=l"(d) : "l"(a), "l"(b), "l"(c));
    return d;
}
__device__ __forceinline__ u64 mul2(u64 a, u64 b) {
    u64 d;
    asm("mul.rn.f32x2 %0, %1, %2;" : "=l"(d) : "l"(a), "l"(b));
    return d;
}
__device__ __forceinline__ void lds2(u64& a, u64& b, u32 addr) {
    asm volatile("ld.shared.v2.u64 {%0, %1}, [%2];" : "=l"(a), "=l"(b) : "r"(addr));
}
__device__ __forceinline__ float2 unpack2(u64 v) {
    float2 f;
    asm("mov.b64 {%0, %1}, %2;" : "=f"(f.x), "=f"(f.y) : "l"(v));
    return f;
}

// Fast exp: scores are tiny (|x| << 1); Taylor deg-8 on |x|<=0.9 (rel err ~1e-6),
// exact expf fallback otherwise (never hit on real data; stale rows are zero-filled).
__device__ __forceinline__ float fast_exp(float x) {
    if (fabsf(x) > 0.9f) return expf(x);
    float r = 1.f/40320.f;
    r = r*x + 1.f/5040.f;
    r = r*x + 1.f/720.f;
    r = r*x + 1.f/120.f;
    r = r*x + 1.f/24.f;
    r = r*x + 1.f/6.f;
    r = r*x + 0.5f;
    r = r*x + 1.f;
    r = r*x + 1.f;
    return r;
}

// ---------------- kernel 1a: projections, K-split x2 -> partials ----------------
// grid (40, 8, 2): x = proj*8 + ptile*2 + kh. Block = [32p x 64h], K = 256. 128 threads.
__global__ void proj_kernel(const float* __restrict__ x,
                            const float* __restrict__ Wk1, const float* __restrict__ Wk2,
                            const float* __restrict__ Wq,  const float* __restrict__ Wv12)
{
    __shared__ __align__(16) float xs[32*33];
    __shared__ __align__(16) float ws[32*68];
    int tid = threadIdx.x;
    int px = blockIdx.x;
    int n  = blockIdx.y;
    int b  = blockIdx.z;
    int proj = px >> 3;
    int p0 = ((px >> 1) & 3) * 32;
    int kh = px & 1;
    int kbase = kh * 256;

    const float* W;
    if (proj == 0)      W = Wk1 + n*DM*DH;
    else if (proj == 1) W = Wk2 + n*DM*DH;
    else if (proj == 2) W = Wq  + n*DM*DH;
    else if (proj == 3) W = Wv12 + n*2*DM*DH;
    else                W = Wv12 + n*2*DM*DH + DM*DH;

    const float* xb = x + b*TS*DM;
    int ty = tid >> 4, tx = tid & 15;      // 8 x 16 threads -> 4p x 4h each
    float acc[4][4];
    #pragma unroll
    for (int p = 0; p < 4; p++)
        #pragma unroll
        for (int c = 0; c < 4; c++) acc[p][c] = 0.f;

    for (int k0 = kbase; k0 < kbase + 256; k0 += 32) {
        #pragma unroll
        for (int r = 0; r < 8; r++) {
            int e = tid + r*128;           // 1024: 32p x 32k
            int pp = e >> 5, kk = e & 31;
            xs[pp*33 + kk] = xb[(p0+pp)*DM + k0 + kk];
        }
        #pragma unroll
        for (int r = 0; r < 16; r++) {
            int e = tid + r*128;           // 2048: 32k x 64h
            int kk = e >> 6, hh = e & 63;
            ws[kk*68 + hh] = W[(k0+kk)*DH + hh];
        }
        __syncthreads();
        #pragma unroll
        for (int k = 0; k < 32; k++) {
            float4 bv = *(const float4*)&ws[k*68 + tx*4];
            #pragma unroll
            for (int p = 0; p < 4; p++) {
                float a = xs[(ty*4+p)*33 + k];
                acc[p][0] += a*bv.x; acc[p][1] += a*bv.y;
                acc[p][2] += a*bv.z; acc[p][3] += a*bv.w;
            }
        }
        __syncthreads();
    }
    int bn = b*NH + n;
    float* dst = g_part + (kh*5 + proj)*131072;
    #pragma unroll
    for (int p = 0; p < 4; p++) {
        int prow = p0 + ty*4 + p;
        float* o = dst + (bn*TS + prow)*DH + tx*4;
        #pragma unroll
        for (int c = 0; c < 4; c++) o[c] = acc[p][c];
    }
}

// ---------------- kernel 1b: reduce K-split partials + bias ----------------
// grid 640, 256 threads, one float4 each (163840 float4 total).
__global__ void proj_reduce(const float* __restrict__ bk1, const float* __restrict__ bk2,
                            const float* __restrict__ bq)
{
    int idx4 = blockIdx.x*256 + threadIdx.x;
    int e = idx4*4;
    int proj = e >> 17;                 // /131072
    int rem  = e & 131071;
    float4 a = *(const float4*)(g_part + proj*131072 + rem);
    float4 bpart = *(const float4*)(g_part + (5+proj)*131072 + rem);
    a.x += bpart.x; a.y += bpart.y; a.z += bpart.z; a.w += bpart.w;

    if (proj < 3) {
        int n = (rem >> 13) & 7;
        int h = rem & 63;
        const float* bias = (proj == 0) ? bk1 : (proj == 1) ? bk2 : bq;
        const float4 bv = *(const float4*)(bias + n*DH + h);
        a.x += bv.x; a.y += bv.y; a.z += bv.z; a.w += bv.w;
    }
    float* dst = (proj == 0) ? g_k1 : (proj == 1) ? g_k2 : (proj == 2) ? g_q
               : (proj == 3) ? g_va : g_vb;
    *(float4*)(dst + rem) = a;
}

// ---------------- kernel 2: FOUR queries per block: raw k1/k2, q folded at tile level ----------
// grid (32, 8, 2), 256 threads = 8 warps. Q = 4x..4x+3. Tiles 8x8 over (s,t), i<=j.
// Per tile lane (p,r): prod = k1[s]*k2[t] (f32x2); acc[q] += prod*q[q] (broadcast q from smem).
#define MAXT 136
__global__ __launch_bounds__(256, 2) void attn_kernel(const float* __restrict__ bv12)
{
    extern __shared__ __align__(16) float sm[];
    float* sk1  = sm;                     // 128 x 68 (phase2: va)
    float* sk2  = sk1 + 128*68;           // 128 x 68 (phase2: vb)
    float* sp   = sk2 + 128*68;           // 4 x MAXT x 16 (per q: row[8], col[8])
    float* srA  = sp  + 4*MAXT*16;        // 4 x 128 row sums
    float* scB  = srA + 4*128;            // 4 x 128 col sums
    float* sq   = scB + 4*128;            // 4 x 64 q-vectors
    float* sden = sq  + 4*64;             // 4

    int tid = threadIdx.x;
    int wid = tid >> 5, lane = tid & 31;
    int p = lane >> 3, r = lane & 7;
    int n = blockIdx.y, b = blockIdx.z;
    int bn = b*NH + n;
    int Q0 = blockIdx.x*4;
    int QD = Q0 + 3;

    int T8 = (QD + 7) >> 3;
    int ntiles = T8*(T8+1)/2;

    // load 4 q-vectors
    const float4* gq4 = (const float4*)(g_q + (bn*TS + Q0)*DH);
    if (tid < 64) ((float4*)sq)[tid] = gq4[tid];   // [q][16 float4] contiguous

    const float4* gk14 = (const float4*)(g_k1 + bn*TS*DH);
    const float4* gk24 = (const float4*)(g_k2 + bn*TS*DH);
    float4* sk14 = (float4*)sk1;
    float4* sk24 = (float4*)sk2;
    u32 k1_b = (u32)__cvta_generic_to_shared(sk1);
    u32 k2_b = (u32)__cvta_generic_to_shared(sk2);
    u32 sq_b = (u32)__cvta_generic_to_shared(sq);

    int nload = QD * 16;                  // rows 0..QD-1
    for (int e = tid; e < nload; e += 256) {
        int s = e >> 4, h4 = e & 15;
        sk14[s*17 + h4] = gk14[e];
        sk24[s*17 + h4] = gk24[e];
    }
    // zero-fill stale rows [QD, 8*T8) so tile math stays on the fast exp path
    float4 zz = make_float4(0.f,0.f,0.f,0.f);
    for (int e = tid; e < (8*T8 - QD)*16; e += 256) {
        int s = QD + (e >> 4), h4 = e & 15;
        sk14[s*17 + h4] = zz;
        sk24[s*17 + h4] = zz;
    }
    __syncthreads();

    const float inv = 1.f/64.f;

    for (int tile = wid; tile < ntiles; tile += 8) {
        // decode tile -> (i, j), i <= j (warp-uniform)
        int j = (int)((sqrtf(8.f*(float)tile + 1.f) - 1.f) * 0.5f);
        while ((j+1)*(j+2)/2 <= tile) j++;
        while (j*(j+1)/2 > tile) j--;
        int i = tile - j*(j+1)/2;
        int s0 = i*8, t0 = j*8;

        u32 aA = k1_b + (s0 + p)*272;             // 17 float4 * 16B row stride
        u32 aB = aA + 4*272;
        u32 aK = k2_b + (t0 + r)*272;
        u64 acc[4][2][2];                          // [q][row][half]
        #pragma unroll
        for (int qq = 0; qq < 4; qq++)
            #pragma unroll
            for (int rr = 0; rr < 2; rr++) { acc[qq][rr][0] = 0ull; acc[qq][rr][1] = 0ull; }

        #pragma unroll
        for (int h4 = 0; h4 < 16; h4++) {
            u64 b0, b1, x0, x1, y0, y1;
            lds2(b0, b1, aK + h4*16);
            lds2(x0, x1, aA + h4*16);
            lds2(y0, y1, aB + h4*16);
            u64 p0a = mul2(x0, b0), p0b = mul2(x1, b1);   // row s0+p
            u64 p1a = mul2(y0, b0), p1b = mul2(y1, b1);   // row s0+p+4
            #pragma unroll
            for (int qq = 0; qq < 4; qq++) {
                u64 q0, q1;
                lds2(q0, q1, sq_b + qq*256 + h4*16);      // broadcast
                acc[qq][0][0] = fma2(p0a, q0, acc[qq][0][0]);
                acc[qq][0][1] = fma2(p0b, q1, acc[qq][0][1]);
                acc[qq][1][0] = fma2(p1a, q0, acc[qq][1][0]);
                acc[qq][1][1] = fma2(p1b, q1, acc[qq][1][1]);
            }
        }

        int sa = s0 + p, sb = sa + 4, t = t0 + r;
        #pragma unroll
        for (int qq = 0; qq < 4; qq++) {
            int Qc = Q0 + qq;
            float2 u0 = unpack2(acc[qq][0][0]), u1 = unpack2(acc[qq][0][1]);
            float a0 = (u0.x + u1.x) + (u0.y + u1.y);
            float2 v0 = unpack2(acc[qq][1][0]), v1 = unpack2(acc[qq][1][1]);
            float a1 = (v0.x + v1.x) + (v0.y + v1.y);

            float e0 = (sa < t && t < Qc) ? fast_exp(a0 * inv) : 0.f;
            float e1 = (sb < t && t < Qc) ? fast_exp(a1 * inv) : 0.f;

            float r0 = e0, r1 = e1;
            #pragma unroll
            for (int o = 4; o > 0; o >>= 1) {
                r0 += __shfl_down_sync(0xffffffffu, r0, o);
                r1 += __shfl_down_sync(0xffffffffu, r1, o);
            }
            float c = e0 + e1;
            c += __shfl_down_sync(0xffffffffu, c, 16);
            c += __shfl_down_sync(0xffffffffu, c, 8);

            float* pp = sp + qq*MAXT*16 + tile*16;
            if (r == 0) { pp[p] = r0; pp[p+4] = r1; }
            if (lane < 8) pp[8 + lane] = c;
        }
    }
    __syncthreads();

    // reload sk1/sk2 with va/vb (serves all four queries)
    {
        const float4* gva4 = (const float4*)(g_va + bn*TS*DH);
        const float4* gvb4 = (const float4*)(g_vb + bn*TS*DH);
        for (int e = tid; e < nload; e += 256) {
            int s = e >> 4, h4 = e & 15;
            sk14[s*17 + h4] = gva4[e];
            sk24[s*17 + h4] = gvb4[e];
        }
    }
    // deterministic row/col reductions for all four queries
    #pragma unroll
    for (int qq = 0; qq < 4; qq++) {
        const float* spq = sp + qq*MAXT*16;
        if (tid < 128) {
            int s = tid, i = s >> 3, pr = s & 7;
            float sum = 0.f;
            if (i < T8) {
                for (int j = i; j < T8; j++)
                    sum += spq[(j*(j+1)/2 + i)*16 + pr];
            }
            srA[qq*128 + s] = sum;
        } else {
            int t = tid - 128, j = t >> 3, rr = t & 7;
            float sum = 0.f;
            if (j < T8) {
                int base = (j*(j+1)/2)*16 + 8 + rr;
                for (int i2 = 0; i2 <= j; i2++) sum += spq[base + i2*16];
            }
            scB[qq*128 + t] = sum;
        }
    }
    __syncthreads();

    // denominators: warp w (0..3) reduces srA of query w
    if (tid < 128) {
        int qq = tid >> 5, l = tid & 31;
        const float* sr = srA + qq*128;
        float v = sr[l] + sr[l+32] + sr[l+64] + sr[l+96];
        #pragma unroll
        for (int o = 16; o > 0; o >>= 1) v += __shfl_down_sync(0xffffffffu, v, o);
        if (l == 0) sden[qq] = v;
    }

    // z sums: thread = (q, h); sum over s
    int zq = tid >> 6;                    // 0..3
    int zh = tid & 63;
    int Qz = Q0 + zq;
    float zacc = 0.f;
    {
        const float* sr = srA + zq*128;
        const float* sc = scB + zq*128;
        for (int s = 0; s < Qz; s++)
            zacc += sr[s]*sk1[s*68 + zh] + sc[s]*sk2[s*68 + zh];
    }
    __syncthreads();
    {
        float den = sden[zq];
        float out = (Qz < 2) ? 0.f : zacc/den + bv12[n*DH + zh];
        g_z[(bn*TS + Qz)*DH + zh] = out;
    }
}

// ---------------- kernel 3: out[b,p,d] = sum_{n,h} z[b,n,p,h] * W_O[n,h,d] + b_O ----------------
// grid (4, 16, 2): [32p x 32d] tile per block, 128 threads, thread = 2p x 4d.
__global__ void out_kernel(const float* __restrict__ Wo, const float* __restrict__ bo,
                           float* __restrict__ out)
{
    __shared__ __align__(16) float zs[32*68];
    __shared__ __align__(16) float ws[64*36];
    int tid = threadIdx.x;
    int p0 = blockIdx.x * 32, d0 = blockIdx.y * 32, b = blockIdx.z;
    int ty = tid >> 3;              // 0..15 -> rows 2ty, 2ty+1
    int tx = tid & 7;               // 0..7  -> d = d0 + tx*4
    float4* zs4 = (float4*)zs;
    float4* ws4 = (float4*)ws;

    float acc[2][4];
    #pragma unroll
    for (int r = 0; r < 2; r++)
        #pragma unroll
        for (int c = 0; c < 4; c++) acc[r][c] = 0.f;

    for (int n = 0; n < NH; n++) {
        const float4* gz4 = (const float4*)(g_z + ((b*NH + n)*TS + p0)*DH);
        #pragma unroll
        for (int r = 0; r < 4; r++) {
            int e = tid + r*128;            // 512 float4: 32p x 16h4
            int p = e >> 4, h4 = e & 15;
            zs4[p*17 + h4] = gz4[p*16 + h4];
        }
        const float* Wn = Wo + n*DH*DM;
        #pragma unroll
        for (int r = 0; r < 4; r++) {
            int e = tid + r*128;            // 512 float4: 64h x 8d4
            int h = e >> 3, d4 = e & 7;
            ws4[h*9 + d4] = *(const float4*)&Wn[h*DM + d0 + d4*4];
        }
        __syncthreads();
        #pragma unroll
        for (int h = 0; h < 64; h++) {
            float4 w = ws4[h*9 + tx];
            float a0 = zs[(ty*2)*68 + h];
            float a1 = zs[(ty*2+1)*68 + h];
            acc[0][0] += a0*w.x; acc[0][1] += a0*w.y; acc[0][2] += a0*w.z; acc[0][3] += a0*w.w;
            acc[1][0] += a1*w.x; acc[1][1] += a1*w.y; acc[1][2] += a1*w.z; acc[1][3] += a1*w.w;
        }
        __syncthreads();
    }
    #pragma unroll
    for (int r = 0; r < 2; r++) {
        int p = p0 + ty*2 + r;
        float* o = out + b*TS*DM + p*DM + d0 + tx*4;
        #pragma unroll
        for (int c = 0; c < 4; c++) o[c] = acc[r][c] + bo[d0 + tx*4 + c];
    }
}

// ---------------- launch ----------------
extern "C" void kernel_launch(void* const* d_in, const int* in_sizes, int n_in,
                              void* d_out, int out_size)
{
    const float* x    = (const float*)d_in[0];
    const float* Wk1  = (const float*)d_in[1];
    const float* Wk2  = (const float*)d_in[2];
    const float* Wq   = (const float*)d_in[3];
    const float* Wv12 = (const float*)d_in[4];
    const float* Wo   = (const float*)d_in[5];
    const float* bk1  = (const float*)d_in[6];
    const float* bk2  = (const float*)d_in[7];
    const float* bq   = (const float*)d_in[8];
    const float* bv12 = (const float*)d_in[9];
    const float* bo   = (const float*)d_in[10];
    float* out = (float*)d_out;

    proj_kernel<<<dim3(40, 8, 2), 128>>>(x, Wk1, Wk2, Wq, Wv12);
    proj_reduce<<<640, 256>>>(bk1, bk2, bq);

    int smem2 = (2*128*68 + 4*MAXT*16 + 4*128*2 + 4*64 + 4)*(int)sizeof(float);  // 109,584 B
    cudaFuncSetAttribute(attn_kernel, cudaFuncAttributeMaxDynamicSharedMemorySize, smem2);
    attn_kernel<<<dim3(32, 8, 2), 256, smem2>>>(bv12);

    out_kernel<<<dim3(4, 16, 2), 128>>>(Wo, bo, out);
}

// round 15
// speedup vs baseline: 1.2400x; 1.0138x over previous
#include <cuda_runtime.h>
#include <stdint.h>
#include <math.h>

#define NH 8
#define TS 128
#define DH 64
#define DM 512

typedef unsigned long long u64;
typedef unsigned int u32;

// ---------------- scratch (static device memory; no allocations) ----------------
__device__ float g_part[10*131072];   // proj partials: [ksplit(2)][proj(5)][bn(16)][p(128)][h(64)]
__device__ float g_k1[2*NH*TS*DH];
__device__ float g_k2[2*NH*TS*DH];
__device__ float g_q [2*NH*TS*DH];
__device__ float g_va[2*NH*TS*DH];
__device__ float g_vb[2*NH*TS*DH];
__device__ float g_z [2*TS*NH*DH];    // TRANSPOSED: [b*128+p][n*64+h]  (256 x 512)
__device__ float g_opart[4*256*512];  // out partials: [ksplit(4)][row(256)][d(512)]

// packed fp32x2 ops (PTX-only; ptxas never auto-fuses)
__device__ __forceinline__ u64 fma2(u64 a, u64 b, u64 c) {
    u64 d;
    asm("fma.rn.f32x2 %0, %1, %2, %3;" : "=l"(d) : "l"(a), "l"(b), "l"(c));
    return d;
}
__device__ __forceinline__ u64 mul2(u64 a, u64 b) {
    u64 d;
    asm("mul.rn.f32x2 %0, %1, %2;" : "=l"(d) : "l"(a), "l"(b));
    return d;
}
__device__ __forceinline__ void lds2(u64& a, u64& b, u32 addr) {
    asm volatile("ld.shared.v2.u64 {%0, %1}, [%2];" : "=l"(a), "=l"(b) : "r"(addr));
}
__device__ __forceinline__ float2 unpack2(u64 v) {
    float2 f;
    asm("mov.b64 {%0, %1}, %2;" : "=f"(f.x), "=f"(f.y) : "l"(v));
    return f;
}

// Fast exp: scores are tiny (|x| << 1); Taylor deg-8 on |x|<=0.9 (rel err ~1e-6),
// exact expf fallback otherwise (never hit on real data; stale rows are zero-filled).
__device__ __forceinline__ float fast_exp(float x) {
    if (fabsf(x) > 0.9f) return expf(x);
    float r = 1.f/40320.f;
    r = r*x + 1.f/5040.f;
    r = r*x + 1.f/720.f;
    r = r*x + 1.f/120.f;
    r = r*x + 1.f/24.f;
    r = r*x + 1.f/6.f;
    r = r*x + 0.5f;
    r = r*x + 1.f;
    r = r*x + 1.f;
    return r;
}

// ---------------- kernel 1a: projections, K-split x2 -> partials ----------------
// grid (40, 8, 2): x = proj*8 + ptile*2 + kh. Block = [32p x 64h], K = 256. 128 threads.
__global__ void proj_kernel(const float* __restrict__ x,
                            const float* __restrict__ Wk1, const float* __restrict__ Wk2,
                            const float* __restrict__ Wq,  const float* __restrict__ Wv12)
{
    __shared__ __align__(16) float xs[32*33];
    __shared__ __align__(16) float ws[32*68];
    int tid = threadIdx.x;
    int px = blockIdx.x;
    int n  = blockIdx.y;
    int b  = blockIdx.z;
    int proj = px >> 3;
    int p0 = ((px >> 1) & 3) * 32;
    int kh = px & 1;
    int kbase = kh * 256;

    const float* W;
    if (proj == 0)      W = Wk1 + n*DM*DH;
    else if (proj == 1) W = Wk2 + n*DM*DH;
    else if (proj == 2) W = Wq  + n*DM*DH;
    else if (proj == 3) W = Wv12 + n*2*DM*DH;
    else                W = Wv12 + n*2*DM*DH + DM*DH;

    const float* xb = x + b*TS*DM;
    int ty = tid >> 4, tx = tid & 15;      // 8 x 16 threads -> 4p x 4h each
    float acc[4][4];
    #pragma unroll
    for (int p = 0; p < 4; p++)
        #pragma unroll
        for (int c = 0; c < 4; c++) acc[p][c] = 0.f;

    for (int k0 = kbase; k0 < kbase + 256; k0 += 32) {
        #pragma unroll
        for (int r = 0; r < 8; r++) {
            int e = tid + r*128;           // 1024: 32p x 32k
            int pp = e >> 5, kk = e & 31;
            xs[pp*33 + kk] = xb[(p0+pp)*DM + k0 + kk];
        }
        #pragma unroll
        for (int r = 0; r < 16; r++) {
            int e = tid + r*128;           // 2048: 32k x 64h
            int kk = e >> 6, hh = e & 63;
            ws[kk*68 + hh] = W[(k0+kk)*DH + hh];
        }
        __syncthreads();
        #pragma unroll
        for (int k = 0; k < 32; k++) {
            float4 bv = *(const float4*)&ws[k*68 + tx*4];
            #pragma unroll
            for (int p = 0; p < 4; p++) {
                float a = xs[(ty*4+p)*33 + k];
                acc[p][0] += a*bv.x; acc[p][1] += a*bv.y;
                acc[p][2] += a*bv.z; acc[p][3] += a*bv.w;
            }
        }
        __syncthreads();
    }
    int bn = b*NH + n;
    float* dst = g_part + (kh*5 + proj)*131072;
    #pragma unroll
    for (int p = 0; p < 4; p++) {
        int prow = p0 + ty*4 + p;
        float* o = dst + (bn*TS + prow)*DH + tx*4;
        #pragma unroll
        for (int c = 0; c < 4; c++) o[c] = acc[p][c];
    }
}

// ---------------- kernel 1b: reduce K-split partials + bias ----------------
// grid 640, 256 threads, one float4 each (163840 float4 total).
__global__ void proj_reduce(const float* __restrict__ bk1, const float* __restrict__ bk2,
                            const float* __restrict__ bq)
{
    int idx4 = blockIdx.x*256 + threadIdx.x;
    int e = idx4*4;
    int proj = e >> 17;                 // /131072
    int rem  = e & 131071;
    float4 a = *(const float4*)(g_part + proj*131072 + rem);
    float4 bpart = *(const float4*)(g_part + (5+proj)*131072 + rem);
    a.x += bpart.x; a.y += bpart.y; a.z += bpart.z; a.w += bpart.w;

    if (proj < 3) {
        int n = (rem >> 13) & 7;
        int h = rem & 63;
        const float* bias = (proj == 0) ? bk1 : (proj == 1) ? bk2 : bq;
        const float4 bv = *(const float4*)(bias + n*DH + h);
        a.x += bv.x; a.y += bv.y; a.z += bv.z; a.w += bv.w;
    }
    float* dst = (proj == 0) ? g_k1 : (proj == 1) ? g_k2 : (proj == 2) ? g_q
               : (proj == 3) ? g_va : g_vb;
    *(float4*)(dst + rem) = a;
}

// ---------------- kernel 2: FOUR queries per block: raw k1/k2, q folded at tile level ----------
// grid (32, 8, 2), 256 threads = 8 warps. Q = 4x..4x+3. Tiles 8x8 over (s,t), i<=j.
// Per tile lane (p,r): prod = k1[s]*k2[t] (f32x2); acc[q] += prod*q[q] (broadcast q from smem).
// z output written TRANSPOSED to g_z[(b*TS+Q)][n*DH+h].
#define MAXT 136
__global__ __launch_bounds__(256, 2) void attn_kernel(const float* __restrict__ bv12)
{
    extern __shared__ __align__(16) float sm[];
    float* sk1  = sm;                     // 128 x 68 (phase2: va)
    float* sk2  = sk1 + 128*68;           // 128 x 68 (phase2: vb)
    float* sp   = sk2 + 128*68;           // 4 x MAXT x 16 (per q: row[8], col[8])
    float* srA  = sp  + 4*MAXT*16;        // 4 x 128 row sums
    float* scB  = srA + 4*128;            // 4 x 128 col sums
    float* sq   = scB + 4*128;            // 4 x 64 q-vectors
    float* sden = sq  + 4*64;             // 4

    int tid = threadIdx.x;
    int wid = tid >> 5, lane = tid & 31;
    int p = lane >> 3, r = lane & 7;
    int n = blockIdx.y, b = blockIdx.z;
    int bn = b*NH + n;
    int Q0 = blockIdx.x*4;
    int QD = Q0 + 3;

    int T8 = (QD + 7) >> 3;
    int ntiles = T8*(T8+1)/2;

    // load 4 q-vectors
    const float4* gq4 = (const float4*)(g_q + (bn*TS + Q0)*DH);
    if (tid < 64) ((float4*)sq)[tid] = gq4[tid];   // [q][16 float4] contiguous

    const float4* gk14 = (const float4*)(g_k1 + bn*TS*DH);
    const float4* gk24 = (const float4*)(g_k2 + bn*TS*DH);
    float4* sk14 = (float4*)sk1;
    float4* sk24 = (float4*)sk2;
    u32 k1_b = (u32)__cvta_generic_to_shared(sk1);
    u32 k2_b = (u32)__cvta_generic_to_shared(sk2);
    u32 sq_b = (u32)__cvta_generic_to_shared(sq);

    int nload = QD * 16;                  // rows 0..QD-1
    for (int e = tid; e < nload; e += 256) {
        int s = e >> 4, h4 = e & 15;
        sk14[s*17 + h4] = gk14[e];
        sk24[s*17 + h4] = gk24[e];
    }
    // zero-fill stale rows [QD, 8*T8) so tile math stays on the fast exp path
    float4 zz = make_float4(0.f,0.f,0.f,0.f);
    for (int e = tid; e < (8*T8 - QD)*16; e += 256) {
        int s = QD + (e >> 4), h4 = e & 15;
        sk14[s*17 + h4] = zz;
        sk24[s*17 + h4] = zz;
    }
    __syncthreads();

    const float inv = 1.f/64.f;

    for (int tile = wid; tile < ntiles; tile += 8) {
        // decode tile -> (i, j), i <= j (warp-uniform)
        int j = (int)((sqrtf(8.f*(float)tile + 1.f) - 1.f) * 0.5f);
        while ((j+1)*(j+2)/2 <= tile) j++;
        while (j*(j+1)/2 > tile) j--;
        int i = tile - j*(j+1)/2;
        int s0 = i*8, t0 = j*8;

        u32 aA = k1_b + (s0 + p)*272;             // 17 float4 * 16B row stride
        u32 aB = aA + 4*272;
        u32 aK = k2_b + (t0 + r)*272;
        u64 acc[4][2][2];                          // [q][row][half]
        #pragma unroll
        for (int qq = 0; qq < 4; qq++)
            #pragma unroll
            for (int rr = 0; rr < 2; rr++) { acc[qq][rr][0] = 0ull; acc[qq][rr][1] = 0ull; }

        #pragma unroll
        for (int h4 = 0; h4 < 16; h4++) {
            u64 b0, b1, x0, x1, y0, y1;
            lds2(b0, b1, aK + h4*16);
            lds2(x0, x1, aA + h4*16);
            lds2(y0, y1, aB + h4*16);
            u64 p0a = mul2(x0, b0), p0b = mul2(x1, b1);   // row s0+p
            u64 p1a = mul2(y0, b0), p1b = mul2(y1, b1);   // row s0+p+4
            #pragma unroll
            for (int qq = 0; qq < 4; qq++) {
                u64 q0, q1;
                lds2(q0, q1, sq_b + qq*256 + h4*16);      // broadcast
                acc[qq][0][0] = fma2(p0a, q0, acc[qq][0][0]);
                acc[qq][0][1] = fma2(p0b, q1, acc[qq][0][1]);
                acc[qq][1][0] = fma2(p1a, q0, acc[qq][1][0]);
                acc[qq][1][1] = fma2(p1b, q1, acc[qq][1][1]);
            }
        }

        int sa = s0 + p, sb = sa + 4, t = t0 + r;
        #pragma unroll
        for (int qq = 0; qq < 4; qq++) {
            int Qc = Q0 + qq;
            float2 u0 = unpack2(acc[qq][0][0]), u1 = unpack2(acc[qq][0][1]);
            float a0 = (u0.x + u1.x) + (u0.y + u1.y);
            float2 v0 = unpack2(acc[qq][1][0]), v1 = unpack2(acc[qq][1][1]);
            float a1 = (v0.x + v1.x) + (v0.y + v1.y);

            float e0 = (sa < t && t < Qc) ? fast_exp(a0 * inv) : 0.f;
            float e1 = (sb < t && t < Qc) ? fast_exp(a1 * inv) : 0.f;

            float r0 = e0, r1 = e1;
            #pragma unroll
            for (int o = 4; o > 0; o >>= 1) {
                r0 += __shfl_down_sync(0xffffffffu, r0, o);
                r1 += __shfl_down_sync(0xffffffffu, r1, o);
            }
            float c = e0 + e1;
            c += __shfl_down_sync(0xffffffffu, c, 16);
            c += __shfl_down_sync(0xffffffffu, c, 8);

            float* pp = sp + qq*MAXT*16 + tile*16;
            if (r == 0) { pp[p] = r0; pp[p+4] = r1; }
            if (lane < 8) pp[8 + lane] = c;
        }
    }
    __syncthreads();

    // reload sk1/sk2 with va/vb (serves all four queries)
    {
        const float4* gva4 = (const float4*)(g_va + bn*TS*DH);
        const float4* gvb4 = (const float4*)(g_vb + bn*TS*DH);
        for (int e = tid; e < nload; e += 256) {
            int s = e >> 4, h4 = e & 15;
            sk14[s*17 + h4] = gva4[e];
            sk24[s*17 + h4] = gvb4[e];
        }
    }
    // deterministic row/col reductions for all four queries
    #pragma unroll
    for (int qq = 0; qq < 4; qq++) {
        const float* spq = sp + qq*MAXT*16;
        if (tid < 128) {
            int s = tid, i = s >> 3, pr = s & 7;
            float sum = 0.f;
            if (i < T8) {
                for (int j = i; j < T8; j++)
                    sum += spq[(j*(j+1)/2 + i)*16 + pr];
            }
            srA[qq*128 + s] = sum;
        } else {
            int t = tid - 128, j = t >> 3, rr = t & 7;
            float sum = 0.f;
            if (j < T8) {
                int base = (j*(j+1)/2)*16 + 8 + rr;
                for (int i2 = 0; i2 <= j; i2++) sum += spq[base + i2*16];
            }
            scB[qq*128 + t] = sum;
        }
    }
    __syncthreads();

    // denominators: warp w (0..3) reduces srA of query w
    if (tid < 128) {
        int qq = tid >> 5, l = tid & 31;
        const float* sr = srA + qq*128;
        float v = sr[l] + sr[l+32] + sr[l+64] + sr[l+96];
        #pragma unroll
        for (int o = 16; o > 0; o >>= 1) v += __shfl_down_sync(0xffffffffu, v, o);
        if (l == 0) sden[qq] = v;
    }

    // z sums: thread = (q, h); sum over s; write TRANSPOSED
    int zq = tid >> 6;                    // 0..3
    int zh = tid & 63;
    int Qz = Q0 + zq;
    float zacc = 0.f;
    {
        const float* sr = srA + zq*128;
        const float* sc = scB + zq*128;
        for (int s = 0; s < Qz; s++)
            zacc += sr[s]*sk1[s*68 + zh] + sc[s]*sk2[s*68 + zh];
    }
    __syncthreads();
    {
        float den = sden[zq];
        float outv = (Qz < 2) ? 0.f : zacc/den + bv12[n*DH + zh];
        g_z[(b*TS + Qz)*(NH*DH) + n*DH + zh] = outv;   // transposed layout
    }
}

// ---------------- kernel 3a: out partials = z[256 x 512] @ Wo[512 x 512], K-split x4 ----------
// grid (8, 16, 4): [32p x 32d] tile, K-chunk 128. 128 threads, thread = 2p x 4d.
__global__ void out_part_kernel(const float* __restrict__ Wo)
{
    __shared__ __align__(16) float zs[32*33];
    __shared__ __align__(16) float ws[32*36];
    int tid = threadIdx.x;
    int p0 = blockIdx.x * 32, d0 = blockIdx.y * 32;
    int ks = blockIdx.z;
    int ty = tid >> 3;              // 0..15 -> rows 2ty, 2ty+1
    int tx = tid & 7;               // 0..7  -> d = d0 + tx*4

    float acc[2][4];
    #pragma unroll
    for (int r = 0; r < 2; r++)
        #pragma unroll
        for (int c = 0; c < 4; c++) acc[r][c] = 0.f;

    for (int kc = 0; kc < 128; kc += 32) {
        int k0 = ks*128 + kc;
        #pragma unroll
        for (int r = 0; r < 8; r++) {
            int e = tid + r*128;            // 1024: 32p x 32k
            int pp = e >> 5, kk = e & 31;
            zs[pp*33 + kk] = g_z[(p0+pp)*512 + k0 + kk];
        }
        #pragma unroll
        for (int r = 0; r < 8; r++) {
            int e = tid + r*128;            // 1024: 32k x 32d
            int kk = e >> 5, dd = e & 31;
            ws[kk*36 + dd] = Wo[(k0+kk)*DM + d0 + dd];
        }
        __syncthreads();
        #pragma unroll
        for (int k = 0; k < 32; k++) {
            float4 w = *(const float4*)&ws[k*36 + tx*4];
            float a0 = zs[(ty*2)*33 + k];
            float a1 = zs[(ty*2+1)*33 + k];
            acc[0][0] += a0*w.x; acc[0][1] += a0*w.y; acc[0][2] += a0*w.z; acc[0][3] += a0*w.w;
            acc[1][0] += a1*w.x; acc[1][1] += a1*w.y; acc[1][2] += a1*w.z; acc[1][3] += a1*w.w;
        }
        __syncthreads();
    }
    float* dst = g_opart + ks*131072;
    #pragma unroll
    for (int r = 0; r < 2; r++) {
        int prow = p0 + ty*2 + r;
        float* o = dst + prow*512 + d0 + tx*4;
        #pragma unroll
        for (int c = 0; c < 4; c++) o[c] = acc[r][c];
    }
}

// ---------------- kernel 3b: reduce 4 out partials + bias ----------------
// grid 128, 256 threads, one float4 each (32768 float4).
__global__ void out_reduce(const float* __restrict__ bo, float* __restrict__ out)
{
    int idx4 = blockIdx.x*256 + threadIdx.x;
    int e = idx4*4;
    int d = e & 511;
    float4 a = *(const float4*)(g_opart + e);
    float4 b1 = *(const float4*)(g_opart + 131072 + e);
    float4 b2 = *(const float4*)(g_opart + 2*131072 + e);
    float4 b3 = *(const float4*)(g_opart + 3*131072 + e);
    float4 bv = *(const float4*)(bo + d);
    a.x = ((a.x + b1.x) + (b2.x + b3.x)) + bv.x;
    a.y = ((a.y + b1.y) + (b2.y + b3.y)) + bv.y;
    a.z = ((a.z + b1.z) + (b2.z + b3.z)) + bv.z;
    a.w = ((a.w + b1.w) + (b2.w + b3.w)) + bv.w;
    *(float4*)(out + e) = a;
}

// ---------------- launch ----------------
extern "C" void kernel_launch(void* const* d_in, const int* in_sizes, int n_in,
                              void* d_out, int out_size)
{
    const float* x    = (const float*)d_in[0];
    const float* Wk1  = (const float*)d_in[1];
    const float* Wk2  = (const float*)d_in[2];
    const float* Wq   = (const float*)d_in[3];
    const float* Wv12 = (const float*)d_in[4];
    const float* Wo   = (const float*)d_in[5];
    const float* bk1  = (const float*)d_in[6];
    const float* bk2  = (const float*)d_in[7];
    const float* bq   = (const float*)d_in[8];
    const float* bv12 = (const float*)d_in[9];
    const float* bo   = (const float*)d_in[10];
    float* out = (float*)d_out;

    proj_kernel<<<dim3(40, 8, 2), 128>>>(x, Wk1, Wk2, Wq, Wv12);
    proj_reduce<<<640, 256>>>(bk1, bk2, bq);

    int smem2 = (2*128*68 + 4*MAXT*16 + 4*128*2 + 4*64 + 4)*(int)sizeof(float);  // 109,584 B
    cudaFuncSetAttribute(attn_kernel, cudaFuncAttributeMaxDynamicSharedMemorySize, smem2);
    attn_kernel<<<dim3(32, 8, 2), 256, smem2>>>(bv12);

    out_part_kernel<<<dim3(8, 16, 4), 128>>>(Wo);
    out_reduce<<<128, 256>>>(bo, out);
}